// round 10
// baseline (speedup 1.0000x reference)
#include <cuda_runtime.h>
#include <math.h>

#define N_SAMPLES   65536
#define N_FRAMES    128
#define NUM_COEFF   6
#define NUM_ACTIVE  7
#define NSER        7
#define NSTAGE      5          // staging slots (4 cp.async groups in flight)
#define KS_THREADS  256
#define TILE_MAX    768

// ---------------- device scratch (no allocation allowed) ----------------
__device__ float  g_y[NSER][N_FRAMES];
__device__ float  g_M[NSER][N_FRAMES];
// pass-1 per-sample data
__device__ float4 g_U1[N_SAMPLES];       // u0..u3  (u = vals of the reference, NEGATIVE)
__device__ float4 g_U2[N_SAMPLES];       // u4,u5,u6, x
__device__ int    g_p[N_SAMPLES];        // p_t = t - 1 - z_t
// pass-2 (expanded window) per-sample data
__device__ float4 g_W0[N_SAMPLES];
__device__ float4 g_W1[N_SAMPLES];
__device__ float4 g_W2[N_SAMPLES];
__device__ float4 g_W3[N_SAMPLES];
__device__ float2 g_D[N_SAMPLES];        // (x_tilde, bitcast ring base B)
__device__ int    g_minz;
__device__ int    g_maxz;
__device__ int    g_flag;
__device__ int    g_spanbad;

// mode helper (must be identical everywhere)
__device__ __forceinline__ void ks_mode(int minz, int maxz, int spanbad,
                                        int& L1, int& L)
{
    L1 = minz + 1;
    if (L1 > 128) L1 = 128;
    int cap1 = 1023 - maxz - NUM_ACTIVE - 1;
    if (L1 > cap1) L1 = cap1;
    if (L1 < 1)  L1 = 1;
    bool noexp = (2 * maxz + 16 + 2 * L1 > 1020);
    L = (noexp || spanbad) ? L1 : 2 * L1;
}
__device__ __forceinline__ bool ks_noexp(int minz, int maxz, int L1)
{
    return (2 * maxz + 16 + 2 * L1 > 1020);
}

// ---------------- kernel A: coeff frames + spline tridiagonal solves -------
__global__ void prep_kernel(const float* __restrict__ delay,
                            const float* __restrict__ raw_gain,
                            const float* __restrict__ raw_coeff)
{
    __shared__ float s_y[NSER][N_FRAMES];
    __shared__ float s_cp[N_FRAMES];
    __shared__ float s_d[NSER][N_FRAMES];
    __shared__ float s_gain;

    const int tid = threadIdx.x;

    if (tid == 0) {
        s_gain = 1.0f / (1.0f + expf(-raw_gain[0]));
        g_minz = 0x7fffffff;
        g_maxz = 0;
        g_flag = 0;
        g_spanbad = 0;
        float c = 0.25f;
        s_cp[0] = c;
        for (int i = 1; i < N_FRAMES - 2; i++) {
            c = 1.0f / (4.0f - c);
            s_cp[i] = c;
        }
    }
    __syncthreads();

    for (int i = tid; i < N_FRAMES * NUM_COEFF; i += blockDim.x) {
        int r = i / NUM_COEFF, c = i % NUM_COEFF;
        s_y[1 + c][r] = 1.0f / (1.0f + expf(-raw_coeff[i]));
    }
    for (int r = tid; r < N_FRAMES; r += blockDim.x)
        s_y[0][r] = delay[r];
    __syncthreads();

    for (int r = tid; r < N_FRAMES; r += blockDim.x) {
        float sum = 0.0f;
        #pragma unroll
        for (int c = 0; c < NUM_COEFF; c++) sum += s_y[1 + c][r];
        float scale = s_gain / sum;
        #pragma unroll
        for (int c = 0; c < NUM_COEFF; c++) s_y[1 + c][r] *= scale;
    }
    __syncthreads();

    if (tid < NSER) {
        const int m = N_FRAMES - 2;
        const float K = 6.0f * 127.0f * 127.0f;
        float* y = s_y[tid];
        float* d = s_d[tid];

        float dp = K * (y[2] - 2.0f * y[1] + y[0]) * 0.25f;
        d[0] = dp;
        for (int i = 1; i < m; i++) {
            float rhs = K * (y[i + 2] - 2.0f * y[i + 1] + y[i]);
            dp = (rhs - dp) * s_cp[i];
            d[i] = dp;
        }
        g_M[tid][0] = 0.0f;
        g_M[tid][N_FRAMES - 1] = 0.0f;
        float Mn = 0.0f;
        for (int i = m - 1; i >= 0; i--) {
            Mn = d[i] - s_cp[i] * Mn;
            g_M[tid][i + 1] = Mn;
        }
    }
    __syncthreads();

    for (int i = tid; i < NSER * N_FRAMES; i += blockDim.x)
        (&g_y[0][0])[i] = (&s_y[0][0])[i];
}

// ---------------- kernel B: per-sample spline eval -> u taps, p, x ---------
// u = vals of the reference (NEGATIVE weights), so the recurrence is exactly
//   y[t] = x[t] - sum_k u[t,k] * y[p_t - k]        (reference form)
__global__ void sample_kernel(const float* __restrict__ exc,
                              const float* __restrict__ burst)
{
    const int t = blockIdx.x * blockDim.x + threadIdx.x;
    if (t >= N_SAMPLES) return;

    const float tt = (float)t * (1.0f / 65535.0f);
    int idx = (int)floorf(tt * 127.0f);
    idx = max(0, min(idx, 126));
    const float s  = tt - (float)idx * (1.0f / 127.0f);
    const float s2 = s * s;
    const float s3 = s2 * s;

    float vout[NSER];
    #pragma unroll
    for (int c = 0; c < NSER; c++) {
        float yi  = g_y[c][idx];
        float yi1 = g_y[c][idx + 1];
        float Mi  = g_M[c][idx];
        float Mi1 = g_M[c][idx + 1];
        float bsl = (yi1 - yi) * 127.0f - (2.0f * Mi + Mi1) * (1.0f / 762.0f);
        vout[c] = yi + bsl * s + 0.5f * Mi * s2 + (Mi1 - Mi) * s3 * (127.0f / 6.0f);
    }

    const float delay_i = vout[0];
    const int   z    = (int)floorf(delay_i);
    const float alfa = delay_i - (float)z;
    const float oma  = 1.0f - alfa;

    // u = vals (pre-negated, matching the reference)
    float u[7];
    u[0] = -oma * vout[1];
    #pragma unroll
    for (int k = 1; k < NUM_COEFF; k++)
        u[k] = -(alfa * vout[k] + oma * vout[k + 1]);
    u[6] = -alfa * vout[NUM_COEFF];

    g_U1[t] = make_float4(u[0], u[1], u[2], u[3]);
    g_U2[t] = make_float4(u[4], u[5], u[6], burst[t]);
    g_p[t]  = t - 1 - z;

    if (exc[t] != 0.0f) atomicExch(&g_flag, 1);

    int wmin = __reduce_min_sync(0xffffffffu, z);
    int wmax = __reduce_max_sync(0xffffffffu, z);
    if ((threadIdx.x & 31) == 0) {
        atomicMin(&g_minz, wmin);
        atomicMax(&g_maxz, wmax);
    }
}

// ---------------- kernel B2: general exc IIR fallback ----------------------
__global__ void exc_scan_kernel(const float* __restrict__ exc,
                                const float* __restrict__ burst)
{
    if (g_flag) {
        float ym1 = 0.0f;
        for (int t = 0; t < N_SAMPLES; t++) {
            ym1 = burst[t] - exc[t] * ym1;
            g_U2[t].w = ym1;
        }
    }
}

// ---------------- kernel B3: build 16-tap dense windows --------------------
// Plain sample:    y = x - sum_k u[k]*y[p-k]       -> window covers [p-6, p]
// Expanded sample (one level of substitution, sign-generic in u):
//   y = (x - sum_k u[k]*x[tau_k]) + sum_{k,j} u[k]*u[tau_k,j]*y[p_tau_k - j]
// stored as  y = x~ - sum_i W[i]*y[wbase+i]  with  W[q-wbase] -= u[k]*u[tau,j].
// Samples with (t mod L2) >= L1 are expanded (their taps can hit the current
// chunk's first half); their expanded reads are provably < chunk start.
// If a window doesn't fit 16 floats, emit plain + set g_spanbad (ks drops to
// L1; both window kinds stay valid at L1 since they read strictly older data).
__global__ void expand_kernel()
{
    __shared__ float4 sU1[TILE_MAX];
    __shared__ float4 sU2[TILE_MAX];
    __shared__ int    sP [TILE_MAX];

    const int tid = threadIdx.x;
    const int t0  = blockIdx.x * blockDim.x;
    const int t   = t0 + tid;

    const int minz = g_minz, maxz = g_maxz;
    int L1, Ldummy;
    ks_mode(minz, maxz, 0, L1, Ldummy);
    const bool noexp = ks_noexp(minz, maxz, L1);
    const int  L2 = 2 * L1;

    int R = 0;
    if (!noexp) {
        R = maxz + 8;                       // tile reach below t0 (<= 509)
        const int tileN = R + (int)blockDim.x;
        for (int i = tid; i < tileN; i += blockDim.x) {
            int tg = t0 - R + i;
            if (tg >= 0 && tg < N_SAMPLES) {
                sU1[i] = g_U1[tg];
                sU2[i] = g_U2[tg];
                sP [i] = g_p[tg];
            } else {
                sU1[i] = make_float4(0, 0, 0, 0);
                sU2[i] = make_float4(0, 0, 0, 0);
                sP [i] = 0;
            }
        }
        __syncthreads();
    }

    if (t >= N_SAMPLES) return;

    float4 U1, U2; int p;
    if (!noexp) { U1 = sU1[R + tid]; U2 = sU2[R + tid]; p = sP[R + tid]; }
    else        { U1 = g_U1[t];      U2 = g_U2[t];      p = g_p[t]; }

    float u[7] = {U1.x, U1.y, U1.z, U1.w, U2.x, U2.y, U2.z};
    float x    = U2.w;

    float W[16];
    #pragma unroll
    for (int i = 0; i < 16; i++) W[i] = 0.0f;
    float xt = x;
    int   wbase = 0;

    const int o = t % L2;
    bool expanded = (!noexp) && (o >= L1);
    bool plain = !expanded;

    if (expanded) {
        // pass 1: min/max of p_tau over valid taps
        int pmin = 0x7fffffff, pmax = -0x7fffffff;
        #pragma unroll
        for (int k = 0; k < 7; k++) {
            int tau = p - k;
            if (tau < 0) continue;
            int pt = sP[tau - t0 + R];
            pmin = min(pmin, pt);
            pmax = max(pmax, pt);
        }
        if (pmin > pmax) {
            wbase = 0;        // all taps reference y[<0] = 0:  y = x
        } else {
            wbase = (pmin - 6) & ~1;
            if (pmax - wbase > 15) {
                atomicExch(&g_spanbad, 1);
                plain = true;               // emit plain window instead
            } else {
                #pragma unroll
                for (int k = 0; k < 7; k++) {
                    int tau = p - k;
                    if (tau < 0) continue;
                    const int ti = tau - t0 + R;
                    const float uk = u[k];
                    float4 V1 = sU1[ti];
                    float4 V2 = sU2[ti];
                    int    pt = sP[ti];
                    xt -= uk * V2.w;
                    const int b = pt - wbase;    // 6..15, taps at b-j
                    W[b    ] -= uk * V1.x;
                    W[b - 1] -= uk * V1.y;
                    W[b - 2] -= uk * V1.z;
                    W[b - 3] -= uk * V1.w;
                    W[b - 4] -= uk * V2.x;
                    W[b - 5] -= uk * V2.y;
                    W[b - 6] -= uk * V2.z;
                }
            }
        }
    }

    if (plain) {
        wbase = (p - 6) & ~1;
        xt = x;
        #pragma unroll
        for (int i = 0; i < 16; i++) W[i] = 0.0f;
        #pragma unroll
        for (int k = 0; k < 7; k++)
            W[p - k - wbase] = u[k];
    }

    g_W0[t] = make_float4(W[0],  W[1],  W[2],  W[3]);
    g_W1[t] = make_float4(W[4],  W[5],  W[6],  W[7]);
    g_W2[t] = make_float4(W[8],  W[9],  W[10], W[11]);
    g_W3[t] = make_float4(W[12], W[13], W[14], W[15]);
    const int B = (int)(((unsigned)wbase) & 1023u);   // low-copy ring base
    g_D[t] = make_float2(xt, __int_as_float(B));
}

// ---------------- cp.async helpers ----------------
__device__ __forceinline__ void cpa16(void* dst_smem, const void* src) {
    unsigned d = (unsigned)__cvta_generic_to_shared(dst_smem);
    asm volatile("cp.async.ca.shared.global [%0], [%1], 16;"
                 :: "r"(d), "l"(src) : "memory");
}
__device__ __forceinline__ void cpa8(void* dst_smem, const void* src) {
    unsigned d = (unsigned)__cvta_generic_to_shared(dst_smem);
    asm volatile("cp.async.ca.shared.global [%0], [%1], 8;"
                 :: "r"(d), "l"(src) : "memory");
}

// ---------------- kernel C: chunk-parallel KS scan (16-tap windows) --------
// 8 warps, one sample per thread per chunk, chunk size L (usually 2*(minz+1)).
// Uniform inner body: 8x LDS.64 window read + 16-FMA dot.  Payload staged via
// cp.async (5 slots, 4 groups in flight).  Duplicated ring: write slot s and
// s+1024; reads use low base B = wbase&1023, indices B..B+15 <= 1038 (high
// region duplicates low slots, so wrapped windows stay contiguous).
// Aliasing/readiness: enforced by ks_mode (L2 mode needs 2*maxz+16+L2<=1020:
// max read-to-write span L2+2*maxz+13 < 1024, no intra-phase slot collision).
__global__ void __launch_bounds__(KS_THREADS, 1) ks_kernel(float* __restrict__ out)
{
    extern __shared__ char dyn[];
    float*  ring = (float*)dyn;                                   // 2048 floats
    float4* st0  = (float4*)(dyn + 8192);                         // [NSTAGE][256]
    float4* st1  = (float4*)(dyn + 8192 + 20480);
    float4* st2  = (float4*)(dyn + 8192 + 40960);
    float4* st3  = (float4*)(dyn + 8192 + 61440);
    float2* stC  = (float2*)(dyn + 8192 + 81920);                 // [NSTAGE][256]
    __shared__ int sL;

    const int tid = threadIdx.x;
    #pragma unroll
    for (int i = tid; i < 2048; i += KS_THREADS) ring[i] = 0.0f;

    if (tid == 0) {
        int L1, L;
        ks_mode(g_minz, g_maxz, g_spanbad, L1, L);
        sL = L;
    }
    __syncthreads();
    const int  L  = sL;
    const bool on = (tid < L);
    const int  nChunks = (N_SAMPLES + L - 1) / L;

    // prologue: chunks 0..3 -> slots 0..3
    #pragma unroll
    for (int s = 0; s < NSTAGE - 1; s++) {
        const int t = s * L + tid;
        if (on && t < N_SAMPLES) {
            cpa16(&st0[s * KS_THREADS + tid], &g_W0[t]);
            cpa16(&st1[s * KS_THREADS + tid], &g_W1[t]);
            cpa16(&st2[s * KS_THREADS + tid], &g_W2[t]);
            cpa16(&st3[s * KS_THREADS + tid], &g_W3[t]);
            cpa8 (&stC[s * KS_THREADS + tid], &g_D[t]);
        }
        asm volatile("cp.async.commit_group;" ::: "memory");
    }

    int    slot = tid & 1023;
    float* outp = out + tid;

    for (int c0 = 0; c0 < nChunks; c0 += NSTAGE) {
        #pragma unroll
        for (int s = 0; s < NSTAGE; s++) {
            const int c = c0 + s;
            if (c < nChunks) {
                asm volatile("cp.async.wait_group 3;" ::: "memory");

                const float4 w0 = st0[s * KS_THREADS + tid];
                const float4 w1 = st1[s * KS_THREADS + tid];
                const float4 w2 = st2[s * KS_THREADS + tid];
                const float4 w3 = st3[s * KS_THREADS + tid];
                const float2 cc = stC[s * KS_THREADS + tid];

                // prefetch chunk c+4 into slot (s+4)%NSTAGE
                const int s4 = (s + NSTAGE - 1) % NSTAGE;
                const int tp = (c + NSTAGE - 1) * L + tid;
                if (on && tp < N_SAMPLES) {
                    cpa16(&st0[s4 * KS_THREADS + tid], &g_W0[tp]);
                    cpa16(&st1[s4 * KS_THREADS + tid], &g_W1[tp]);
                    cpa16(&st2[s4 * KS_THREADS + tid], &g_W2[tp]);
                    cpa16(&st3[s4 * KS_THREADS + tid], &g_W3[tp]);
                    cpa8 (&stC[s4 * KS_THREADS + tid], &g_D[tp]);
                }
                asm volatile("cp.async.commit_group;" ::: "memory");

                const int t = c * L + tid;
                if (on && t < N_SAMPLES) {
                    const int B = __float_as_int(cc.y);
                    float2 f0 = *reinterpret_cast<const float2*>(&ring[B     ]);
                    float2 f1 = *reinterpret_cast<const float2*>(&ring[B +  2]);
                    float2 f2 = *reinterpret_cast<const float2*>(&ring[B +  4]);
                    float2 f3 = *reinterpret_cast<const float2*>(&ring[B +  6]);
                    float2 f4 = *reinterpret_cast<const float2*>(&ring[B +  8]);
                    float2 f5 = *reinterpret_cast<const float2*>(&ring[B + 10]);
                    float2 f6 = *reinterpret_cast<const float2*>(&ring[B + 12]);
                    float2 f7 = *reinterpret_cast<const float2*>(&ring[B + 14]);
                    float m0 = fmaf(w0.x, f0.x, w0.y * f0.y);
                    float m1 = fmaf(w0.z, f1.x, w0.w * f1.y);
                    float m2 = fmaf(w1.x, f2.x, w1.y * f2.y);
                    float m3 = fmaf(w1.z, f3.x, w1.w * f3.y);
                    float m4 = fmaf(w2.x, f4.x, w2.y * f4.y);
                    float m5 = fmaf(w2.z, f5.x, w2.w * f5.y);
                    float m6 = fmaf(w3.x, f6.x, w3.y * f6.y);
                    float m7 = fmaf(w3.z, f7.x, w3.w * f7.y);
                    float y  = cc.x - (((m0 + m1) + (m2 + m3)) + ((m4 + m5) + (m6 + m7)));
                    ring[slot]        = y;
                    ring[slot + 1024] = y;
                    *outp = y;
                }
                __syncthreads();

                slot = (slot + L) & 1023;
                outp += L;
            }
        }
    }
}

// ---------------- launcher ----------------
extern "C" void kernel_launch(void* const* d_in, const int* in_sizes, int n_in,
                              void* d_out, int out_size)
{
    const float* delay     = (const float*)d_in[0];  // [128]
    const float* raw_gain  = (const float*)d_in[1];  // [1]
    const float* raw_coeff = (const float*)d_in[2];  // [128,6]
    const float* exc       = (const float*)d_in[3];  // [1,65536,1]
    const float* burst     = (const float*)d_in[4];  // [65536]
    float* out = (float*)d_out;

    const int dynsmem = 8192 + 4 * (NSTAGE * KS_THREADS * 16) + NSTAGE * KS_THREADS * 8;
    static bool attr_done = false;
    if (!attr_done) {
        cudaFuncSetAttribute(ks_kernel, cudaFuncAttributeMaxDynamicSharedMemorySize, dynsmem);
        attr_done = true;
    }

    prep_kernel<<<1, 256>>>(delay, raw_gain, raw_coeff);
    sample_kernel<<<N_SAMPLES / 256, 256>>>(exc, burst);
    exc_scan_kernel<<<1, 1>>>(exc, burst);
    expand_kernel<<<N_SAMPLES / 256, 256>>>();
    ks_kernel<<<1, KS_THREADS, dynsmem>>>(out);
}